// round 11
// baseline (speedup 1.0000x reference)
#include <cuda_runtime.h>
#include <cuda_bf16.h>
#include <math.h>
#include <stdint.h>

// ---------------- scratch (static device globals; no allocation) ----------------
__device__ float g_buf1[32u*128*128*64];   // conv1 out
__device__ float g_buf2[32u*64*64*128];    // conv2 out
__device__ float g_buf3[32u*32*32*256];    // conv3 out
__device__ float g_featA[32u*256*512];
__device__ float g_featB[32u*256*512];
__device__ float g_corr[32u*256*256];
__device__ float g_r1[32u*10*10*128];
__device__ float g_r2[32u*6*6*64];
__device__ float g_geo[32*18];

// fp32 -> 3-term bf16 split (hi+mid+lo ~ 24 mantissa bits), two floats packed
// per u32 at each level (first arg in low half = lower k index).
__device__ __forceinline__ void cvt3(float a, float b,
                                     uint32_t& hi, uint32_t& mid, uint32_t& lo) {
    __nv_bfloat162 h = __floats2bfloat162_rn(a, b);
    float ra = a - __bfloat162float(__low2bfloat16(h));
    float rb = b - __bfloat162float(__high2bfloat16(h));
    __nv_bfloat162 m = __floats2bfloat162_rn(ra, rb);
    ra -= __bfloat162float(__low2bfloat16(m));
    rb -= __bfloat162float(__high2bfloat16(m));
    __nv_bfloat162 l = __floats2bfloat162_rn(ra, rb);
    hi  = reinterpret_cast<uint32_t&>(h);
    mid = reinterpret_cast<uint32_t&>(m);
    lo  = reinterpret_cast<uint32_t&>(l);
}

__device__ __forceinline__ void mma16816(float* d, const uint32_t* a, const uint32_t* b) {
    asm volatile(
        "mma.sync.aligned.m16n8k16.row.col.f32.bf16.bf16.f32 "
        "{%0,%1,%2,%3}, {%4,%5,%6,%7}, {%8,%9}, {%0,%1,%2,%3};"
        : "+f"(d[0]), "+f"(d[1]), "+f"(d[2]), "+f"(d[3])
        : "r"(a[0]), "r"(a[1]), "r"(a[2]), "r"(a[3]), "r"(b[0]), "r"(b[1]));
}
// variant with c = 0 (starts a fresh accumulation window)
__device__ __forceinline__ void mma16816_zc(float* d, const uint32_t* a, const uint32_t* b) {
    asm volatile(
        "mma.sync.aligned.m16n8k16.row.col.f32.bf16.bf16.f32 "
        "{%0,%1,%2,%3}, {%4,%5,%6,%7}, {%8,%9}, {%10,%11,%12,%13};"
        : "=f"(d[0]), "=f"(d[1]), "=f"(d[2]), "=f"(d[3])
        : "r"(a[0]), "r"(a[1]), "r"(a[2]), "r"(a[3]), "r"(b[0]), "r"(b[1]),
          "f"(0.f), "f"(0.f), "f"(0.f), "f"(0.f));
}

// smem layout in u32 units: rows padded to 33 u32 (bank-conflict-free)
#define A_STRIDE 33
#define SM_AHI  0
#define SM_AMID (128*33)
#define SM_ALO  (2*128*33)
#define SM_BHI  (3*128*33)
#define SM_BMID (3*128*33 + 64*33)
#define SM_BLO  (3*128*33 + 2*64*33)
#define SM_U32  (3*128*33 + 3*64*33)     // 19008 u32 = 76032 bytes

// ====== bf16x6 tensor-core implicit-GEMM conv / GEMM =====
// Per-k16 accumulation windows drained into IEEE-RN fp32 registers: the HMMA
// fp32 accumulator is truncation-biased (~2^-24 per chained accumulate, linear
// in K); short windows + FADD drain restore fp32-class error growth.
// Block tile M=128, N=64, BK=64; 8 warps (4M x 2N), warp tile 32x32.
template<int CIN,int COUT,int HIN,int WIN,int HOUT,int WOUT,int KH,int KW,int STRIDE,
         bool MGUARD,bool BKM,int NTOT,bool RELU>
__global__ __launch_bounds__(256)
void conv_mma(const float* __restrict__ in, const float* __restrict__ wt,
              float* __restrict__ out)
{
    constexpr int M   = HOUT * WOUT;
    constexpr int CPT = CIN / 64;
    constexpr int KCH = KH * KW * CPT;

    extern __shared__ uint32_t smem[];
    uint32_t* Ahi  = smem + SM_AHI;
    uint32_t* Amid = smem + SM_AMID;
    uint32_t* Alo  = smem + SM_ALO;
    uint32_t* Bhi  = smem + SM_BHI;
    uint32_t* Bmid = smem + SM_BMID;
    uint32_t* Blo  = smem + SM_BLO;

    int tid = threadIdx.x;
    int wid = tid >> 5, lane = tid & 31;
    int m0 = blockIdx.x * 128, n0 = blockIdx.y * 64;
    int img = blockIdx.z;
    const float* inb = in + (size_t)img * HIN * WIN * CIN;

    // A producer: 2 threads per row, 32 k each
    int ar = tid >> 1;
    int ak0 = (tid & 1) * 32;
    int am = m0 + ar;
    int aoh = am / WOUT, aow = am % WOUT;

    // warp tiling
    int wm = wid >> 1, wn = wid & 1;          // warp m 0..3, n 0..1
    int g = lane >> 2, t = lane & 3;

    float acc[2][4][4];
    #pragma unroll
    for (int i = 0; i < 2; ++i)
        #pragma unroll
        for (int j = 0; j < 4; ++j)
            #pragma unroll
            for (int q = 0; q < 4; ++q) acc[i][j][q] = 0.f;

    for (int c = 0; c < KCH; ++c) {
        int tap  = c / CPT;
        int cin0 = (c % CPT) * 64;
        int kh = tap / KW, kw = tap - kh * KW;

        // ---- A: 128 x 64 fp32 -> bf16 hi/mid/lo pairs
        {
            int ih = aoh * STRIDE + kh, iw = aow * STRIDE + kw;
            bool ok = (ih < HIN) && (iw < WIN);
            if (MGUARD) ok = ok && (am < M);
            const float* base = inb + ((size_t)ih * WIN + iw) * CIN + cin0 + ak0;
            #pragma unroll
            for (int j = 0; j < 8; ++j) {
                float4 v = ok ? *reinterpret_cast<const float4*>(base + 4*j)
                              : make_float4(0.f,0.f,0.f,0.f);
                uint32_t h0,m0_,l0,h1,m1,l1;
                cvt3(v.x, v.y, h0, m0_, l0);
                cvt3(v.z, v.w, h1, m1, l1);
                int p = (ak0 >> 1) + 2*j;          // k-pair index
                Ahi [ar*A_STRIDE + p]     = h0;
                Ahi [ar*A_STRIDE + p + 1] = h1;
                Amid[ar*A_STRIDE + p]     = m0_;
                Amid[ar*A_STRIDE + p + 1] = m1;
                Alo [ar*A_STRIDE + p]     = l0;
                Alo [ar*A_STRIDE + p + 1] = l1;
            }
        }
        // ---- B: 64(n) x 64(k)
        if (BKM) {
            int br = tid >> 2;                  // 0..63
            int bk0 = (tid & 3) * 16;
            const float* base = wt + ((size_t)img * NTOT + n0 + br) * CIN + cin0 + bk0;
            #pragma unroll
            for (int j = 0; j < 4; ++j) {
                float4 v = *reinterpret_cast<const float4*>(base + 4*j);
                uint32_t h0,m0_,l0,h1,m1,l1;
                cvt3(v.x, v.y, h0, m0_, l0);
                cvt3(v.z, v.w, h1, m1, l1);
                int p = (bk0 >> 1) + 2*j;
                Bhi [br*A_STRIDE + p]     = h0;
                Bhi [br*A_STRIDE + p + 1] = h1;
                Bmid[br*A_STRIDE + p]     = m0_;
                Bmid[br*A_STRIDE + p + 1] = m1;
                Blo [br*A_STRIDE + p]     = l0;
                Blo [br*A_STRIDE + p + 1] = l1;
            }
        } else {
            #pragma unroll
            for (int it = 0; it < 2; ++it) {
                int item = it * 256 + tid;       // 0..511
                int kp = item >> 4;              // k-pair 0..31
                int n4 = (item & 15) * 4;
                int k  = kp * 2;
                const float* wr = wt + ((size_t)(tap * CIN + cin0 + k)) * COUT + n0 + n4;
                float4 w0 = *reinterpret_cast<const float4*>(wr);
                float4 w1 = *reinterpret_cast<const float4*>(wr + COUT);
                float a0[4] = {w0.x, w0.y, w0.z, w0.w};
                float a1[4] = {w1.x, w1.y, w1.z, w1.w};
                #pragma unroll
                for (int j = 0; j < 4; ++j) {
                    uint32_t h, m, l;
                    cvt3(a0[j], a1[j], h, m, l);
                    Bhi [(n4 + j)*A_STRIDE + kp] = h;
                    Bmid[(n4 + j)*A_STRIDE + kp] = m;
                    Blo [(n4 + j)*A_STRIDE + kp] = l;
                }
            }
        }
        __syncthreads();

        // ---- compute: 4 k16 steps; each is a fresh MMA window drained via FADD
        #pragma unroll
        for (int ks = 0; ks < 4; ++ks) {
            int kp = ks * 8;
            uint32_t ah[2][4], am_[2][4], al[2][4];
            #pragma unroll
            for (int mt = 0; mt < 2; ++mt) {
                int rm = wm * 32 + mt * 16;
                int r0 = (rm + g    )*A_STRIDE + kp;
                int r1 = (rm + g + 8)*A_STRIDE + kp;
                ah[mt][0] = Ahi [r0 + t];     ah[mt][1] = Ahi [r1 + t];
                ah[mt][2] = Ahi [r0 + 4 + t]; ah[mt][3] = Ahi [r1 + 4 + t];
                am_[mt][0] = Amid[r0 + t];     am_[mt][1] = Amid[r1 + t];
                am_[mt][2] = Amid[r0 + 4 + t]; am_[mt][3] = Amid[r1 + 4 + t];
                al[mt][0] = Alo [r0 + t];     al[mt][1] = Alo [r1 + t];
                al[mt][2] = Alo [r0 + 4 + t]; al[mt][3] = Alo [r1 + 4 + t];
            }
            #pragma unroll
            for (int nt = 0; nt < 4; ++nt) {
                int nb = (wn * 32 + nt * 8 + g)*A_STRIDE + kp;
                uint32_t bh[2], bm[2], bl[2];
                bh[0] = Bhi [nb + t]; bh[1] = Bhi [nb + 4 + t];
                bm[0] = Bmid[nb + t]; bm[1] = Bmid[nb + 4 + t];
                bl[0] = Blo [nb + t]; bl[1] = Blo [nb + 4 + t];
                #pragma unroll
                for (int mt = 0; mt < 2; ++mt) {
                    float tmp[4];
                    // fresh window (c=0), then 5 chained accumulates
                    mma16816_zc(tmp, ah[mt],  bh);
                    mma16816(tmp, ah[mt],  bm);
                    mma16816(tmp, am_[mt], bh);
                    mma16816(tmp, ah[mt],  bl);
                    mma16816(tmp, am_[mt], bm);
                    mma16816(tmp, al[mt],  bh);
                    // IEEE-RN drain
                    acc[mt][nt][0] += tmp[0];
                    acc[mt][nt][1] += tmp[1];
                    acc[mt][nt][2] += tmp[2];
                    acc[mt][nt][3] += tmp[3];
                }
            }
        }
        __syncthreads();
    }

    // ---- epilogue
    #pragma unroll
    for (int mt = 0; mt < 2; ++mt) {
        #pragma unroll
        for (int half = 0; half < 2; ++half) {
            int row = m0 + wm * 32 + mt * 16 + g + half * 8;
            if (MGUARD && row >= M) continue;
            float* op = out + ((size_t)img * M + row) * COUT + n0 + wn * 32;
            #pragma unroll
            for (int nt = 0; nt < 4; ++nt) {
                float x0 = acc[mt][nt][half*2 + 0];
                float x1 = acc[mt][nt][half*2 + 1];
                if (RELU) { x0 = fmaxf(x0, 0.f); x1 = fmaxf(x1, 0.f); }
                *reinterpret_cast<float2*>(op + nt*8 + 2*t) = make_float2(x0, x1);
            }
        }
    }
}

// ---------------- conv1: 256x256x3 -> 128x128x64, stride 2, SAME(pad_lo=0) ----
__global__ void conv1_kernel(const float* __restrict__ in, const float* __restrict__ w,
                             float* __restrict__ out)
{
    int idx = blockIdx.x * 256 + threadIdx.x;
    int oc = idx & 63;
    int p  = idx >> 6;
    int ow = p & 127; p >>= 7;
    int oh = p & 127; p >>= 7;
    int b  = p;
    float acc = 0.f;
    #pragma unroll
    for (int kh = 0; kh < 3; ++kh) {
        int ih = oh * 2 + kh;
        if (ih >= 256) continue;
        #pragma unroll
        for (int kw = 0; kw < 3; ++kw) {
            int iw = ow * 2 + kw;
            if (iw >= 256) continue;
            const float* ip = in + ((size_t)(b * 256 + ih) * 256 + iw) * 3;
            const float* wp = w + ((kh * 3 + kw) * 3) * 64 + oc;
            acc += ip[0] * wp[0] + ip[1] * wp[64] + ip[2] * wp[128];
        }
    }
    out[idx] = fmaxf(acc, 0.f);
}

// ---------------- legacy FFMA igemm (small r2 conv only) ----------------------
template<int CIN,int COUT,int HIN,int WIN,int HOUT,int WOUT,int KH,int KW,int STRIDE,bool MGUARD>
__global__ __launch_bounds__(256)
void conv_igemm(const float* __restrict__ in, const float* __restrict__ wt,
                float* __restrict__ out)
{
    constexpr int M   = HOUT * WOUT;
    constexpr int CPT = CIN / 64;
    constexpr int KCH = KH * KW * CPT;
    __shared__ __align__(16) float As[64][68];
    __shared__ __align__(16) float Bs[64][68];

    int tid = threadIdx.x;
    int m0 = blockIdx.x * 64, n0 = blockIdx.y * 64;
    int img = blockIdx.z;
    const float* inb = in + (size_t)img * HIN * WIN * CIN;

    int lr = tid >> 2;
    int lc = (tid & 3) << 4;
    int m  = m0 + lr;
    int oh = m / WOUT, ow = m % WOUT;
    int ty = tid >> 4, tx = tid & 15;

    float acc[4][4] = {};
    for (int c = 0; c < KCH; ++c) {
        int tap  = c / CPT;
        int cin0 = (c % CPT) * 64;
        int kh = tap / KW, kw = tap - kh * KW;
        int ih = oh * STRIDE + kh, iw = ow * STRIDE + kw;
        bool ok = (ih < HIN) && (iw < WIN);
        if (MGUARD) ok = ok && (m < M);
        const float* ap = inb + ((size_t)ih * WIN + iw) * CIN + cin0 + lc;
        #pragma unroll
        for (int t = 0; t < 4; ++t) {
            float4 v = ok ? *reinterpret_cast<const float4*>(ap + 4 * t)
                          : make_float4(0.f, 0.f, 0.f, 0.f);
            As[lc + 4*t + 0][lr] = v.x; As[lc + 4*t + 1][lr] = v.y;
            As[lc + 4*t + 2][lr] = v.z; As[lc + 4*t + 3][lr] = v.w;
        }
        const float* bp = wt + ((size_t)tap * CIN + cin0 + lr) * COUT + n0 + lc;
        #pragma unroll
        for (int t = 0; t < 4; ++t)
            *reinterpret_cast<float4*>(&Bs[lr][lc + 4*t]) =
                *reinterpret_cast<const float4*>(bp + 4 * t);
        __syncthreads();
        #pragma unroll
        for (int kk = 0; kk < 64; ++kk) {
            float4 av = *reinterpret_cast<const float4*>(&As[kk][ty * 4]);
            float4 bv = *reinterpret_cast<const float4*>(&Bs[kk][tx * 4]);
            float ar[4] = {av.x, av.y, av.z, av.w};
            float br[4] = {bv.x, bv.y, bv.z, bv.w};
            #pragma unroll
            for (int i = 0; i < 4; ++i)
                #pragma unroll
                for (int j = 0; j < 4; ++j)
                    acc[i][j] += ar[i] * br[j];
        }
        __syncthreads();
    }
    #pragma unroll
    for (int i = 0; i < 4; ++i) {
        int mm = m0 + ty * 4 + i;
        if (MGUARD && mm >= M) continue;
        float4 v = make_float4(fmaxf(acc[i][0], 0.f), fmaxf(acc[i][1], 0.f),
                               fmaxf(acc[i][2], 0.f), fmaxf(acc[i][3], 0.f));
        *reinterpret_cast<float4*>(out + ((size_t)img * M + mm) * COUT + n0 + tx * 4) = v;
    }
}

// ---------------- L2-normalize over 512 channels ------------------------------
__global__ void normalize_kernel(float* __restrict__ feat)
{
    float* p = feat + (size_t)blockIdx.x * 512;
    int tid = threadIdx.x;   // 128
    float v0 = p[tid], v1 = p[tid + 128], v2 = p[tid + 256], v3 = p[tid + 384];
    float s = v0*v0 + v1*v1 + v2*v2 + v3*v3;
    for (int o = 16; o > 0; o >>= 1) s += __shfl_down_sync(0xffffffffu, s, o);
    __shared__ float sw[4];
    __shared__ float sscale;
    if ((tid & 31) == 0) sw[tid >> 5] = s;
    __syncthreads();
    if (tid == 0) sscale = 1.f / (sqrtf(sw[0] + sw[1] + sw[2] + sw[3]) + 1e-6f);
    __syncthreads();
    float sc = sscale;
    p[tid] = v0 * sc; p[tid + 128] = v1 * sc; p[tid + 256] = v2 * sc; p[tid + 384] = v3 * sc;
}

// ---------------- dense: geo = r2_flat(2304) @ Wd(2304,18) + bd ---------------
__global__ void dense_kernel(const float* __restrict__ x, const float* __restrict__ Wd,
                             const float* __restrict__ bd, float* __restrict__ geo)
{
    int b = blockIdx.x;
    int o = threadIdx.x >> 5;
    int lane = threadIdx.x & 31;
    const float* xb = x + b * 2304;
    float acc = 0.f;
    for (int t = lane; t < 2304; t += 32)
        acc += xb[t] * Wd[t * 18 + o];
    for (int s = 16; s > 0; s >>= 1) acc += __shfl_down_sync(0xffffffffu, acc, s);
    if (lane == 0) geo[b * 18 + o] = acc + bd[o];
}

// ---------------- TPS fit + masked sum ----------------------------------------
__global__ void tps_sum_kernel(const float* __restrict__ geo, const float* __restrict__ corr,
                               float* __restrict__ out)
{
    int b = blockIdx.x, tid = threadIdx.x;
    __shared__ float sdx[9], sdy[9], swx[9], swy[9], sax[3], say[3];
    __shared__ float red[256];

    if (tid == 0) {
        const float srcx[9] = {0.f, 0.5f, 1.f, 0.f, 0.5f, 1.f, 0.f, 5.f, 1.f};
        const float srcy[9] = {0.f, 0.f,  0.f, 0.5f,0.5f, 0.5f,1.f, 1.f, 1.f};
        float dx9[9], dy9[9], vx[9], vy[9];
        for (int c = 0; c < 9; ++c) {
            float mx_ = geo[b * 18 + 2 * c], my_ = geo[b * 18 + 2 * c + 1];
            dx9[c] = srcx[c] + mx_;  dy9[c] = srcy[c] + my_;
            vx[c] = -mx_;            vy[c] = -my_;
        }
        float Mx[12][14];
        for (int i = 0; i < 12; ++i)
            for (int j = 0; j < 14; ++j) Mx[i][j] = 0.f;
        for (int i = 0; i < 9; ++i) {
            for (int j = 0; j < 9; ++j) {
                float ddx = dx9[i] - dx9[j], ddy = dy9[i] - dy9[j];
                float r = sqrtf(ddx * ddx + ddy * ddy + 1e-12f);
                Mx[i][j] = r * r * logf(r + 1e-6f);
            }
            Mx[i][9] = 1.f; Mx[i][10] = dx9[i]; Mx[i][11] = dy9[i];
            Mx[9][i] = 1.f; Mx[10][i] = dx9[i]; Mx[11][i] = dy9[i];
            Mx[i][12] = vx[i]; Mx[i][13] = vy[i];
        }
        for (int k = 0; k < 12; ++k) {
            int piv = k; float best = fabsf(Mx[k][k]);
            for (int i = k + 1; i < 12; ++i) {
                float a = fabsf(Mx[i][k]);
                if (a > best) { best = a; piv = i; }
            }
            if (piv != k)
                for (int j = k; j < 14; ++j) {
                    float t = Mx[k][j]; Mx[k][j] = Mx[piv][j]; Mx[piv][j] = t;
                }
            for (int i = k + 1; i < 12; ++i) {
                float f = Mx[i][k] / Mx[k][k];
                for (int j = k + 1; j < 14; ++j) Mx[i][j] -= f * Mx[k][j];
                Mx[i][k] = 0.f;
            }
        }
        float thx[12], thy[12];
        for (int k = 11; k >= 0; --k) {
            float sx = Mx[k][12], sy = Mx[k][13];
            for (int j = k + 1; j < 12; ++j) { sx -= Mx[k][j] * thx[j]; sy -= Mx[k][j] * thy[j]; }
            thx[k] = sx / Mx[k][k];  thy[k] = sy / Mx[k][k];
        }
        float s8x = 0.f, s8y = 0.f;
        for (int c = 1; c < 9; ++c) { s8x += thx[c]; s8y += thy[c]; }
        swx[0] = -s8x; swy[0] = -s8y;
        for (int c = 1; c < 9; ++c) { swx[c] = thx[c]; swy[c] = thy[c]; }
        sax[0] = thx[9]; sax[1] = thx[10]; sax[2] = thx[11];
        say[0] = thy[9]; say[1] = thy[10]; say[2] = thy[11];
        for (int c = 0; c < 9; ++c) { sdx[c] = dx9[c]; sdy[c] = dy9[c]; }
    }
    __syncthreads();

    int r = tid >> 4, c = tid & 15;
    float px = c * (1.f / 15.f), py = r * (1.f / 15.f);
    float zx = 0.f, zy = 0.f;
    #pragma unroll
    for (int q = 0; q < 9; ++q) {
        float ddx = px - sdx[q], ddy = py - sdy[q];
        float rr = sqrtf(ddx * ddx + ddy * ddy + 1e-12f);
        float u = rr * rr * logf(rr + 1e-6f);
        zx += u * swx[q]; zy += u * swy[q];
    }
    zx += sax[0] + px * sax[1] + py * sax[2];
    zy += say[0] + px * say[1] + py * say[2];
    float axv = (px + zx) * 15.f;
    float ayv = (py + zy) * 15.f;

    const float* col = corr + (size_t)b * 65536 + tid;
    float s = 0.f;
    for (int i = 0; i < 16; ++i) {
        if (fabsf((float)i - ayv) > 1.f) continue;
        const float* rp = col + i * 4096;
        for (int j = 0; j < 16; ++j)
            if (fabsf((float)j - axv) <= 1.f) s += rp[j * 256];
    }
    red[tid] = s;
    __syncthreads();
    for (int o = 128; o > 0; o >>= 1) {
        if (tid < o) red[tid] += red[tid + o];
        __syncthreads();
    }
    if (tid == 0) out[b] = red[0];
}

// ---------------- launch ------------------------------------------------------
extern "C" void kernel_launch(void* const* d_in, const int* in_sizes, int n_in,
                              void* d_out, int out_size)
{
    const float* imgA = (const float*)d_in[0];
    const float* imgB = (const float*)d_in[1];
    const float* W1   = (const float*)d_in[2];
    const float* W2   = (const float*)d_in[3];
    const float* W3   = (const float*)d_in[4];
    const float* W4   = (const float*)d_in[5];
    const float* Wr1  = (const float*)d_in[6];
    const float* Wr2  = (const float*)d_in[7];
    const float* Wd   = (const float*)d_in[8];
    const float* bd   = (const float*)d_in[9];
    float* out = (float*)d_out;

    float *buf1, *buf2, *buf3, *featA, *featB, *corr, *r1, *r2, *geo;
    cudaGetSymbolAddress((void**)&buf1,  g_buf1);
    cudaGetSymbolAddress((void**)&buf2,  g_buf2);
    cudaGetSymbolAddress((void**)&buf3,  g_buf3);
    cudaGetSymbolAddress((void**)&featA, g_featA);
    cudaGetSymbolAddress((void**)&featB, g_featB);
    cudaGetSymbolAddress((void**)&corr,  g_corr);
    cudaGetSymbolAddress((void**)&r1,    g_r1);
    cudaGetSymbolAddress((void**)&r2,    g_r2);
    cudaGetSymbolAddress((void**)&geo,   g_geo);

    const int SMB = SM_U32 * 4;    // 76032 bytes dynamic smem
    auto mm2 = conv_mma<64, 128, 128, 128, 64, 64, 3, 3, 2, false, false, 0, true>;
    auto mm3 = conv_mma<128, 256, 64, 64, 32, 32, 3, 3, 2, false, false, 0, true>;
    auto mm4 = conv_mma<256, 512, 32, 32, 16, 16, 3, 3, 2, false, false, 0, true>;
    auto mmc = conv_mma<512, 256, 16, 16, 16, 16, 1, 1, 1, false, true, 256, false>;
    auto mr1 = conv_mma<256, 128, 16, 16, 10, 10, 7, 7, 1, true, false, 0, true>;
    cudaFuncSetAttribute(mm2, cudaFuncAttributeMaxDynamicSharedMemorySize, SMB);
    cudaFuncSetAttribute(mm3, cudaFuncAttributeMaxDynamicSharedMemorySize, SMB);
    cudaFuncSetAttribute(mm4, cudaFuncAttributeMaxDynamicSharedMemorySize, SMB);
    cudaFuncSetAttribute(mmc, cudaFuncAttributeMaxDynamicSharedMemorySize, SMB);
    cudaFuncSetAttribute(mr1, cudaFuncAttributeMaxDynamicSharedMemorySize, SMB);

    for (int im = 0; im < 2; ++im) {
        const float* img = im ? imgB : imgA;
        float* feat = im ? featB : featA;
        conv1_kernel<<<131072, 256>>>(img, W1, buf1);
        mm2<<<dim3(32, 2, 32), 256, SMB>>>(buf1, W2, buf2);
        mm3<<<dim3(8, 4, 32), 256, SMB>>>(buf2, W3, buf3);
        mm4<<<dim3(2, 8, 32), 256, SMB>>>(buf3, W4, feat);
        normalize_kernel<<<8192, 128>>>(feat);
    }

    mmc<<<dim3(2, 4, 32), 256, SMB>>>(featA, featB, corr);

    mr1<<<dim3(1, 2, 32), 256, SMB>>>(corr, Wr1, r1);
    conv_igemm<128, 64, 10, 10, 6, 6, 5, 5, 1, true>
        <<<dim3(1, 1, 32), 256>>>(r1, Wr2, r2);

    dense_kernel<<<32, 576>>>(r2, Wd, bd, geo);
    tps_sum_kernel<<<32, 256>>>(geo, corr, out);
}

// round 12
// speedup vs baseline: 1.4594x; 1.4594x over previous
#include <cuda_runtime.h>
#include <cuda_bf16.h>
#include <math.h>
#include <stdint.h>

// ---------------- scratch (static device globals; no allocation) ----------------
__device__ float g_buf1[32u*128*128*64];   // conv1 out
__device__ float g_buf2[32u*64*64*128];    // conv2 out
__device__ float g_buf3[32u*32*32*256];    // conv3 out
__device__ float g_featA[32u*256*512];
__device__ float g_featB[32u*256*512];
__device__ float g_corr[32u*256*256];
__device__ float g_r1[32u*10*10*128];
__device__ float g_r2[32u*6*6*64];
__device__ float g_geo[32*18];
__device__ float g_wtx[3153920];           // transposed weights (k-major per n)

// fp32 -> 3-term bf16 split (hi+mid+lo ~ 24 mantissa bits), two floats packed
// per u32 at each level (first arg in low half = lower k index).
__device__ __forceinline__ void cvt3(float a, float b,
                                     uint32_t& hi, uint32_t& mid, uint32_t& lo) {
    __nv_bfloat162 h = __floats2bfloat162_rn(a, b);
    float ra = a - __bfloat162float(__low2bfloat16(h));
    float rb = b - __bfloat162float(__high2bfloat16(h));
    __nv_bfloat162 m = __floats2bfloat162_rn(ra, rb);
    ra -= __bfloat162float(__low2bfloat16(m));
    rb -= __bfloat162float(__high2bfloat16(m));
    __nv_bfloat162 l = __floats2bfloat162_rn(ra, rb);
    hi  = reinterpret_cast<uint32_t&>(h);
    mid = reinterpret_cast<uint32_t&>(m);
    lo  = reinterpret_cast<uint32_t&>(l);
}

__device__ __forceinline__ void mma16816(float* d, const uint32_t* a, const uint32_t* b) {
    asm volatile(
        "mma.sync.aligned.m16n8k16.row.col.f32.bf16.bf16.f32 "
        "{%0,%1,%2,%3}, {%4,%5,%6,%7}, {%8,%9}, {%0,%1,%2,%3};"
        : "+f"(d[0]), "+f"(d[1]), "+f"(d[2]), "+f"(d[3])
        : "r"(a[0]), "r"(a[1]), "r"(a[2]), "r"(a[3]), "r"(b[0]), "r"(b[1]));
}
__device__ __forceinline__ void mma16816_zc(float* d, const uint32_t* a, const uint32_t* b) {
    asm volatile(
        "mma.sync.aligned.m16n8k16.row.col.f32.bf16.bf16.f32 "
        "{%0,%1,%2,%3}, {%4,%5,%6,%7}, {%8,%9}, {%10,%11,%12,%13};"
        : "=f"(d[0]), "=f"(d[1]), "=f"(d[2]), "=f"(d[3])
        : "r"(a[0]), "r"(a[1]), "r"(a[2]), "r"(a[3]), "r"(b[0]), "r"(b[1]),
          "f"(0.f), "f"(0.f), "f"(0.f), "f"(0.f));
}
__device__ __forceinline__ void ldm4(uint32_t* r, uint32_t addr) {
    asm volatile("ldmatrix.sync.aligned.m8n8.x4.shared.b16 {%0,%1,%2,%3}, [%4];"
                 : "=r"(r[0]), "=r"(r[1]), "=r"(r[2]), "=r"(r[3]) : "r"(addr));
}
__device__ __forceinline__ uint32_t smem_addr_u32(const void* p) {
    uint32_t a;
    asm("{ .reg .u64 t; cvta.to.shared.u64 t, %1; cvt.u32.u64 %0, t; }" : "=r"(a) : "l"(p));
    return a;
}

// smem layout in u32 units: rows padded to 36 u32 (144B: 16B-aligned rows for
// ldmatrix; 8 consecutive rows cover all 8 16B bank-groups -> conflict-free)
#define A_STRIDE 36
#define SM_AHI  0
#define SM_AMID (128*36)
#define SM_ALO  (2*128*36)
#define SM_BHI  (3*128*36)
#define SM_BMID (3*128*36 + 64*36)
#define SM_BLO  (3*128*36 + 2*64*36)
#define SM_U32  (3*128*36 + 3*64*36)     // 20736 u32 = 82944 bytes

// ====== bf16x6 tensor-core implicit-GEMM conv / GEMM ======
// Per-k16 windows drained into IEEE-RN fp32 regs (HMMA accumulator truncation
// fix, validated R11). Fragments via ldmatrix.x4; producers use STS.128.
// Block tile M=128, N=64, BK=64; 8 warps (4M x 2N), warp tile 32x32.
// B (weights) must be k-major per n-row: W'[(tap*COUT + n)*CIN + cin]
// (pre-transposed), or (img, NTOT, CIN) for BKM (correlation).
template<int CIN,int COUT,int HIN,int WIN,int HOUT,int WOUT,int KH,int KW,int STRIDE,
         bool MGUARD,bool BKM,int NTOT,bool RELU>
__global__ __launch_bounds__(256, 2)
void conv_mma(const float* __restrict__ in, const float* __restrict__ wt,
              float* __restrict__ out)
{
    constexpr int M   = HOUT * WOUT;
    constexpr int CPT = CIN / 64;
    constexpr int KCH = KH * KW * CPT;

    extern __shared__ uint32_t smem[];
    uint32_t* Ahi  = smem + SM_AHI;
    uint32_t* Amid = smem + SM_AMID;
    uint32_t* Alo  = smem + SM_ALO;
    uint32_t* Bhi  = smem + SM_BHI;
    uint32_t* Bmid = smem + SM_BMID;
    uint32_t* Blo  = smem + SM_BLO;
    uint32_t sb = smem_addr_u32(smem);
    uint32_t sbAhi = sb + SM_AHI*4,  sbAmid = sb + SM_AMID*4, sbAlo = sb + SM_ALO*4;
    uint32_t sbBhi = sb + SM_BHI*4,  sbBmid = sb + SM_BMID*4, sbBlo = sb + SM_BLO*4;

    int tid = threadIdx.x;
    int wid = tid >> 5, lane = tid & 31;
    int m0 = blockIdx.x * 128, n0 = blockIdx.y * 64;
    int img = blockIdx.z;
    const float* inb = in + (size_t)img * HIN * WIN * CIN;

    // A producer: 2 threads per row, 32 k each
    int ar = tid >> 1;
    int ak0 = (tid & 1) * 32;
    int am = m0 + ar;
    int aoh = am / WOUT, aow = am % WOUT;

    // B producer: 4 threads per row, 16 k each
    int br = tid >> 2;
    int bk0 = (tid & 3) * 16;

    // warp tiling
    int wm = wid >> 1, wn = wid & 1;          // warp m 0..3, n 0..1
    int g = lane >> 2, t = lane & 3;

    // ldmatrix per-lane address offsets (u32 units)
    int arsel = ((lane >> 3) & 1) * 8 + (lane & 7);
    int acol  = (lane >> 4) * 4;
    int aoffs[2];
    #pragma unroll
    for (int mt = 0; mt < 2; ++mt)
        aoffs[mt] = (wm*32 + mt*16 + arsel) * A_STRIDE + acol;
    int brsel = ((lane >> 4) & 1) * 8 + (lane & 7);
    int bcol  = ((lane >> 3) & 1) * 4;
    int boffs[2];
    #pragma unroll
    for (int ntp = 0; ntp < 2; ++ntp)
        boffs[ntp] = (wn*32 + ntp*16 + brsel) * A_STRIDE + bcol;

    float acc[2][4][4];
    #pragma unroll
    for (int i = 0; i < 2; ++i)
        #pragma unroll
        for (int j = 0; j < 4; ++j)
            #pragma unroll
            for (int q = 0; q < 4; ++q) acc[i][j][q] = 0.f;

    for (int c = 0; c < KCH; ++c) {
        int tap  = c / CPT;
        int cin0 = (c % CPT) * 64;
        int kh = tap / KW, kw = tap - kh * KW;

        // ---- A: 128 x 64 fp32 -> bf16 hi/mid/lo, STS.128
        {
            int ih = aoh * STRIDE + kh, iw = aow * STRIDE + kw;
            bool ok = (ih < HIN) && (iw < WIN);
            if (MGUARD) ok = ok && (am < M);
            const float* base = inb + ((size_t)ih * WIN + iw) * CIN + cin0 + ak0;
            #pragma unroll
            for (int jj = 0; jj < 4; ++jj) {
                float4 v0 = ok ? *reinterpret_cast<const float4*>(base + jj*8)
                               : make_float4(0.f,0.f,0.f,0.f);
                float4 v1 = ok ? *reinterpret_cast<const float4*>(base + jj*8 + 4)
                               : make_float4(0.f,0.f,0.f,0.f);
                uint32_t h[4], m[4], l[4];
                cvt3(v0.x, v0.y, h[0], m[0], l[0]);
                cvt3(v0.z, v0.w, h[1], m[1], l[1]);
                cvt3(v1.x, v1.y, h[2], m[2], l[2]);
                cvt3(v1.z, v1.w, h[3], m[3], l[3]);
                int p = (ak0 >> 1) + jj*4;
                *reinterpret_cast<uint4*>(&Ahi [ar*A_STRIDE + p]) = *reinterpret_cast<uint4*>(h);
                *reinterpret_cast<uint4*>(&Amid[ar*A_STRIDE + p]) = *reinterpret_cast<uint4*>(m);
                *reinterpret_cast<uint4*>(&Alo [ar*A_STRIDE + p]) = *reinterpret_cast<uint4*>(l);
            }
        }
        // ---- B: 64(n) x 64(k), k-major source (transposed weights or corr fB)
        {
            const float* base = BKM
                ? wt + ((size_t)img * NTOT + n0 + br) * CIN + cin0 + bk0
                : wt + ((size_t)tap * COUT + n0 + br) * CIN + cin0 + bk0;
            #pragma unroll
            for (int jj = 0; jj < 2; ++jj) {
                float4 v0 = *reinterpret_cast<const float4*>(base + jj*8);
                float4 v1 = *reinterpret_cast<const float4*>(base + jj*8 + 4);
                uint32_t h[4], m[4], l[4];
                cvt3(v0.x, v0.y, h[0], m[0], l[0]);
                cvt3(v0.z, v0.w, h[1], m[1], l[1]);
                cvt3(v1.x, v1.y, h[2], m[2], l[2]);
                cvt3(v1.z, v1.w, h[3], m[3], l[3]);
                int p = (bk0 >> 1) + jj*4;
                *reinterpret_cast<uint4*>(&Bhi [br*A_STRIDE + p]) = *reinterpret_cast<uint4*>(h);
                *reinterpret_cast<uint4*>(&Bmid[br*A_STRIDE + p]) = *reinterpret_cast<uint4*>(m);
                *reinterpret_cast<uint4*>(&Blo [br*A_STRIDE + p]) = *reinterpret_cast<uint4*>(l);
            }
        }
        __syncthreads();

        // ---- compute: 4 k16 steps; fresh MMA window per step, FADD drain
        #pragma unroll
        for (int ks = 0; ks < 4; ++ks) {
            int kp = ks * 8;
            uint32_t ah[2][4], am_[2][4], al[2][4];
            #pragma unroll
            for (int mt = 0; mt < 2; ++mt) {
                ldm4(ah[mt],  sbAhi  + (aoffs[mt] + kp) * 4);
                ldm4(am_[mt], sbAmid + (aoffs[mt] + kp) * 4);
                ldm4(al[mt],  sbAlo  + (aoffs[mt] + kp) * 4);
            }
            #pragma unroll
            for (int ntp = 0; ntp < 2; ++ntp) {
                uint32_t bh[4], bm[4], bl[4];
                ldm4(bh, sbBhi  + (boffs[ntp] + kp) * 4);
                ldm4(bm, sbBmid + (boffs[ntp] + kp) * 4);
                ldm4(bl, sbBlo  + (boffs[ntp] + kp) * 4);
                #pragma unroll
                for (int half = 0; half < 2; ++half) {
                    int nt = ntp * 2 + half;
                    const uint32_t* pbh = bh + half*2;
                    const uint32_t* pbm = bm + half*2;
                    const uint32_t* pbl = bl + half*2;
                    #pragma unroll
                    for (int mt = 0; mt < 2; ++mt) {
                        float tmp[4];
                        mma16816_zc(tmp, ah[mt],  pbh);
                        mma16816(tmp, ah[mt],  pbm);
                        mma16816(tmp, am_[mt], pbh);
                        mma16816(tmp, ah[mt],  pbl);
                        mma16816(tmp, am_[mt], pbm);
                        mma16816(tmp, al[mt],  pbh);
                        acc[mt][nt][0] += tmp[0];
                        acc[mt][nt][1] += tmp[1];
                        acc[mt][nt][2] += tmp[2];
                        acc[mt][nt][3] += tmp[3];
                    }
                }
            }
        }
        __syncthreads();
    }

    // ---- epilogue
    #pragma unroll
    for (int mt = 0; mt < 2; ++mt) {
        #pragma unroll
        for (int half = 0; half < 2; ++half) {
            int row = m0 + wm * 32 + mt * 16 + g + half * 8;
            if (MGUARD && row >= M) continue;
            float* op = out + ((size_t)img * M + row) * COUT + n0 + wn * 32;
            #pragma unroll
            for (int nt = 0; nt < 4; ++nt) {
                float x0 = acc[mt][nt][half*2 + 0];
                float x1 = acc[mt][nt][half*2 + 1];
                if (RELU) { x0 = fmaxf(x0, 0.f); x1 = fmaxf(x1, 0.f); }
                *reinterpret_cast<float2*>(op + nt*8 + 2*t) = make_float2(x0, x1);
            }
        }
    }
}

// ---------------- weight transpose: (tap,cin,cout) -> (tap,cout,cin) ----------
__global__ void transpose_w(const float* __restrict__ in, float* __restrict__ out,
                            int cin, int cout, int total)
{
    int idx = blockIdx.x * 256 + threadIdx.x;
    if (idx >= total) return;
    int n = idx % cout;
    int rest = idx / cout;
    int ci = rest % cin;
    int tap = rest / cin;
    out[((size_t)tap * cout + n) * cin + ci] = in[idx];
}

// ---------------- conv1: 256x256x3 -> 128x128x64, stride 2, SAME(pad_lo=0) ----
__global__ void conv1_kernel(const float* __restrict__ in, const float* __restrict__ w,
                             float* __restrict__ out)
{
    int idx = blockIdx.x * 256 + threadIdx.x;
    int oc = idx & 63;
    int p  = idx >> 6;
    int ow = p & 127; p >>= 7;
    int oh = p & 127; p >>= 7;
    int b  = p;
    float acc = 0.f;
    #pragma unroll
    for (int kh = 0; kh < 3; ++kh) {
        int ih = oh * 2 + kh;
        if (ih >= 256) continue;
        #pragma unroll
        for (int kw = 0; kw < 3; ++kw) {
            int iw = ow * 2 + kw;
            if (iw >= 256) continue;
            const float* ip = in + ((size_t)(b * 256 + ih) * 256 + iw) * 3;
            const float* wp = w + ((kh * 3 + kw) * 3) * 64 + oc;
            acc += ip[0] * wp[0] + ip[1] * wp[64] + ip[2] * wp[128];
        }
    }
    out[idx] = fmaxf(acc, 0.f);
}

// ---------------- legacy FFMA igemm (small r2 conv only) ----------------------
template<int CIN,int COUT,int HIN,int WIN,int HOUT,int WOUT,int KH,int KW,int STRIDE,bool MGUARD>
__global__ __launch_bounds__(256)
void conv_igemm(const float* __restrict__ in, const float* __restrict__ wt,
                float* __restrict__ out)
{
    constexpr int M   = HOUT * WOUT;
    constexpr int CPT = CIN / 64;
    constexpr int KCH = KH * KW * CPT;
    __shared__ __align__(16) float As[64][68];
    __shared__ __align__(16) float Bs[64][68];

    int tid = threadIdx.x;
    int m0 = blockIdx.x * 64, n0 = blockIdx.y * 64;
    int img = blockIdx.z;
    const float* inb = in + (size_t)img * HIN * WIN * CIN;

    int lr = tid >> 2;
    int lc = (tid & 3) << 4;
    int m  = m0 + lr;
    int oh = m / WOUT, ow = m % WOUT;
    int ty = tid >> 4, tx = tid & 15;

    float acc[4][4] = {};
    for (int c = 0; c < KCH; ++c) {
        int tap  = c / CPT;
        int cin0 = (c % CPT) * 64;
        int kh = tap / KW, kw = tap - kh * KW;
        int ih = oh * STRIDE + kh, iw = ow * STRIDE + kw;
        bool ok = (ih < HIN) && (iw < WIN);
        if (MGUARD) ok = ok && (m < M);
        const float* ap = inb + ((size_t)ih * WIN + iw) * CIN + cin0 + lc;
        #pragma unroll
        for (int t = 0; t < 4; ++t) {
            float4 v = ok ? *reinterpret_cast<const float4*>(ap + 4 * t)
                          : make_float4(0.f, 0.f, 0.f, 0.f);
            As[lc + 4*t + 0][lr] = v.x; As[lc + 4*t + 1][lr] = v.y;
            As[lc + 4*t + 2][lr] = v.z; As[lc + 4*t + 3][lr] = v.w;
        }
        const float* bp = wt + ((size_t)tap * CIN + cin0 + lr) * COUT + n0 + lc;
        #pragma unroll
        for (int t = 0; t < 4; ++t)
            *reinterpret_cast<float4*>(&Bs[lr][lc + 4*t]) =
                *reinterpret_cast<const float4*>(bp + 4 * t);
        __syncthreads();
        #pragma unroll
        for (int kk = 0; kk < 64; ++kk) {
            float4 av = *reinterpret_cast<const float4*>(&As[kk][ty * 4]);
            float4 bv = *reinterpret_cast<const float4*>(&Bs[kk][tx * 4]);
            float ar[4] = {av.x, av.y, av.z, av.w};
            float br[4] = {bv.x, bv.y, bv.z, bv.w};
            #pragma unroll
            for (int i = 0; i < 4; ++i)
                #pragma unroll
                for (int j = 0; j < 4; ++j)
                    acc[i][j] += ar[i] * br[j];
        }
        __syncthreads();
    }
    #pragma unroll
    for (int i = 0; i < 4; ++i) {
        int mm = m0 + ty * 4 + i;
        if (MGUARD && mm >= M) continue;
        float4 v = make_float4(fmaxf(acc[i][0], 0.f), fmaxf(acc[i][1], 0.f),
                               fmaxf(acc[i][2], 0.f), fmaxf(acc[i][3], 0.f));
        *reinterpret_cast<float4*>(out + ((size_t)img * M + mm) * COUT + n0 + tx * 4) = v;
    }
}

// ---------------- L2-normalize over 512 channels ------------------------------
__global__ void normalize_kernel(float* __restrict__ feat)
{
    float* p = feat + (size_t)blockIdx.x * 512;
    int tid = threadIdx.x;   // 128
    float v0 = p[tid], v1 = p[tid + 128], v2 = p[tid + 256], v3 = p[tid + 384];
    float s = v0*v0 + v1*v1 + v2*v2 + v3*v3;
    for (int o = 16; o > 0; o >>= 1) s += __shfl_down_sync(0xffffffffu, s, o);
    __shared__ float sw[4];
    __shared__ float sscale;
    if ((tid & 31) == 0) sw[tid >> 5] = s;
    __syncthreads();
    if (tid == 0) sscale = 1.f / (sqrtf(sw[0] + sw[1] + sw[2] + sw[3]) + 1e-6f);
    __syncthreads();
    float sc = sscale;
    p[tid] = v0 * sc; p[tid + 128] = v1 * sc; p[tid + 256] = v2 * sc; p[tid + 384] = v3 * sc;
}

// ---------------- dense: geo = r2_flat(2304) @ Wd(2304,18) + bd ---------------
__global__ void dense_kernel(const float* __restrict__ x, const float* __restrict__ Wd,
                             const float* __restrict__ bd, float* __restrict__ geo)
{
    int b = blockIdx.x;
    int o = threadIdx.x >> 5;
    int lane = threadIdx.x & 31;
    const float* xb = x + b * 2304;
    float acc = 0.f;
    for (int t = lane; t < 2304; t += 32)
        acc += xb[t] * Wd[t * 18 + o];
    for (int s = 16; s > 0; s >>= 1) acc += __shfl_down_sync(0xffffffffu, acc, s);
    if (lane == 0) geo[b * 18 + o] = acc + bd[o];
}

// ---------------- TPS fit + masked sum ----------------------------------------
__global__ void tps_sum_kernel(const float* __restrict__ geo, const float* __restrict__ corr,
                               float* __restrict__ out)
{
    int b = blockIdx.x, tid = threadIdx.x;
    __shared__ float sdx[9], sdy[9], swx[9], swy[9], sax[3], say[3];
    __shared__ float red[256];

    if (tid == 0) {
        const float srcx[9] = {0.f, 0.5f, 1.f, 0.f, 0.5f, 1.f, 0.f, 5.f, 1.f};
        const float srcy[9] = {0.f, 0.f,  0.f, 0.5f,0.5f, 0.5f,1.f, 1.f, 1.f};
        float dx9[9], dy9[9], vx[9], vy[9];
        for (int c = 0; c < 9; ++c) {
            float mx_ = geo[b * 18 + 2 * c], my_ = geo[b * 18 + 2 * c + 1];
            dx9[c] = srcx[c] + mx_;  dy9[c] = srcy[c] + my_;
            vx[c] = -mx_;            vy[c] = -my_;
        }
        float Mx[12][14];
        for (int i = 0; i < 12; ++i)
            for (int j = 0; j < 14; ++j) Mx[i][j] = 0.f;
        for (int i = 0; i < 9; ++i) {
            for (int j = 0; j < 9; ++j) {
                float ddx = dx9[i] - dx9[j], ddy = dy9[i] - dy9[j];
                float r = sqrtf(ddx * ddx + ddy * ddy + 1e-12f);
                Mx[i][j] = r * r * logf(r + 1e-6f);
            }
            Mx[i][9] = 1.f; Mx[i][10] = dx9[i]; Mx[i][11] = dy9[i];
            Mx[9][i] = 1.f; Mx[10][i] = dx9[i]; Mx[11][i] = dy9[i];
            Mx[i][12] = vx[i]; Mx[i][13] = vy[i];
        }
        for (int k = 0; k < 12; ++k) {
            int piv = k; float best = fabsf(Mx[k][k]);
            for (int i = k + 1; i < 12; ++i) {
                float a = fabsf(Mx[i][k]);
                if (a > best) { best = a; piv = i; }
            }
            if (piv != k)
                for (int j = k; j < 14; ++j) {
                    float t = Mx[k][j]; Mx[k][j] = Mx[piv][j]; Mx[piv][j] = t;
                }
            for (int i = k + 1; i < 12; ++i) {
                float f = Mx[i][k] / Mx[k][k];
                for (int j = k + 1; j < 14; ++j) Mx[i][j] -= f * Mx[k][j];
                Mx[i][k] = 0.f;
            }
        }
        float thx[12], thy[12];
        for (int k = 11; k >= 0; --k) {
            float sx = Mx[k][12], sy = Mx[k][13];
            for (int j = k + 1; j < 12; ++j) { sx -= Mx[k][j] * thx[j]; sy -= Mx[k][j] * thy[j]; }
            thx[k] = sx / Mx[k][k];  thy[k] = sy / Mx[k][k];
        }
        float s8x = 0.f, s8y = 0.f;
        for (int c = 1; c < 9; ++c) { s8x += thx[c]; s8y += thy[c]; }
        swx[0] = -s8x; swy[0] = -s8y;
        for (int c = 1; c < 9; ++c) { swx[c] = thx[c]; swy[c] = thy[c]; }
        sax[0] = thx[9]; sax[1] = thx[10]; sax[2] = thx[11];
        say[0] = thy[9]; say[1] = thy[10]; say[2] = thy[11];
        for (int c = 0; c < 9; ++c) { sdx[c] = dx9[c]; sdy[c] = dy9[c]; }
    }
    __syncthreads();

    int r = tid >> 4, c = tid & 15;
    float px = c * (1.f / 15.f), py = r * (1.f / 15.f);
    float zx = 0.f, zy = 0.f;
    #pragma unroll
    for (int q = 0; q < 9; ++q) {
        float ddx = px - sdx[q], ddy = py - sdy[q];
        float rr = sqrtf(ddx * ddx + ddy * ddy + 1e-12f);
        float u = rr * rr * logf(rr + 1e-6f);
        zx += u * swx[q]; zy += u * swy[q];
    }
    zx += sax[0] + px * sax[1] + py * sax[2];
    zy += say[0] + px * say[1] + py * say[2];
    float axv = (px + zx) * 15.f;
    float ayv = (py + zy) * 15.f;

    const float* col = corr + (size_t)b * 65536 + tid;
    float s = 0.f;
    for (int i = 0; i < 16; ++i) {
        if (fabsf((float)i - ayv) > 1.f) continue;
        const float* rp = col + i * 4096;
        for (int j = 0; j < 16; ++j)
            if (fabsf((float)j - axv) <= 1.f) s += rp[j * 256];
    }
    red[tid] = s;
    __syncthreads();
    for (int o = 128; o > 0; o >>= 1) {
        if (tid < o) red[tid] += red[tid + o];
        __syncthreads();
    }
    if (tid == 0) out[b] = red[0];
}

// ---------------- launch ------------------------------------------------------
extern "C" void kernel_launch(void* const* d_in, const int* in_sizes, int n_in,
                              void* d_out, int out_size)
{
    const float* imgA = (const float*)d_in[0];
    const float* imgB = (const float*)d_in[1];
    const float* W1   = (const float*)d_in[2];
    const float* W2   = (const float*)d_in[3];
    const float* W3   = (const float*)d_in[4];
    const float* W4   = (const float*)d_in[5];
    const float* Wr1  = (const float*)d_in[6];
    const float* Wr2  = (const float*)d_in[7];
    const float* Wd   = (const float*)d_in[8];
    const float* bd   = (const float*)d_in[9];
    float* out = (float*)d_out;

    float *buf1, *buf2, *buf3, *featA, *featB, *corr, *r1, *r2, *geo, *wtx;
    cudaGetSymbolAddress((void**)&buf1,  g_buf1);
    cudaGetSymbolAddress((void**)&buf2,  g_buf2);
    cudaGetSymbolAddress((void**)&buf3,  g_buf3);
    cudaGetSymbolAddress((void**)&featA, g_featA);
    cudaGetSymbolAddress((void**)&featB, g_featB);
    cudaGetSymbolAddress((void**)&corr,  g_corr);
    cudaGetSymbolAddress((void**)&r1,    g_r1);
    cudaGetSymbolAddress((void**)&r2,    g_r2);
    cudaGetSymbolAddress((void**)&geo,   g_geo);
    cudaGetSymbolAddress((void**)&wtx,   g_wtx);

    // transposed-weight regions
    float* W2T  = wtx;                 // 9*64*128    = 73728
    float* W3T  = wtx + 73728;         // 9*128*256   = 294912
    float* W4T  = wtx + 368640;        // 9*256*512   = 1179648
    float* Wr1T = wtx + 1548288;       // 49*256*128  = 1605632

    transpose_w<<<(73728 + 255)/256, 256>>>(W2, W2T, 64, 128, 73728);
    transpose_w<<<(294912 + 255)/256, 256>>>(W3, W3T, 128, 256, 294912);
    transpose_w<<<(1179648 + 255)/256, 256>>>(W4, W4T, 256, 512, 1179648);
    transpose_w<<<(1605632 + 255)/256, 256>>>(Wr1, Wr1T, 256, 128, 1605632);

    const int SMB = SM_U32 * 4;    // 82944 bytes dynamic smem
    auto mm2 = conv_mma<64, 128, 128, 128, 64, 64, 3, 3, 2, false, false, 0, true>;
    auto mm3 = conv_mma<128, 256, 64, 64, 32, 32, 3, 3, 2, false, false, 0, true>;
    auto mm4 = conv_mma<256, 512, 32, 32, 16, 16, 3, 3, 2, false, false, 0, true>;
    auto mmc = conv_mma<512, 256, 16, 16, 16, 16, 1, 1, 1, false, true, 256, false>;
    auto mr1 = conv_mma<256, 128, 16, 16, 10, 10, 7, 7, 1, true, false, 0, true>;
    cudaFuncSetAttribute(mm2, cudaFuncAttributeMaxDynamicSharedMemorySize, SMB);
    cudaFuncSetAttribute(mm3, cudaFuncAttributeMaxDynamicSharedMemorySize, SMB);
    cudaFuncSetAttribute(mm4, cudaFuncAttributeMaxDynamicSharedMemorySize, SMB);
    cudaFuncSetAttribute(mmc, cudaFuncAttributeMaxDynamicSharedMemorySize, SMB);
    cudaFuncSetAttribute(mr1, cudaFuncAttributeMaxDynamicSharedMemorySize, SMB);

    for (int im = 0; im < 2; ++im) {
        const float* img = im ? imgB : imgA;
        float* feat = im ? featB : featA;
        conv1_kernel<<<131072, 256>>>(img, W1, buf1);
        mm2<<<dim3(32, 2, 32), 256, SMB>>>(buf1, W2T, buf2);
        mm3<<<dim3(8, 4, 32), 256, SMB>>>(buf2, W3T, buf3);
        mm4<<<dim3(2, 8, 32), 256, SMB>>>(buf3, W4T, feat);
        normalize_kernel<<<8192, 128>>>(feat);
    }

    mmc<<<dim3(2, 4, 32), 256, SMB>>>(featA, featB, corr);

    mr1<<<dim3(1, 2, 32), 256, SMB>>>(corr, Wr1T, r1);
    conv_igemm<128, 64, 10, 10, 6, 6, 5, 5, 1, true>
        <<<dim3(1, 1, 32), 256>>>(r1, Wr2, r2);

    dense_kernel<<<32, 576>>>(r2, Wd, bd, geo);
    tps_sum_kernel<<<32, 256>>>(geo, corr, out);
}

// round 13
// speedup vs baseline: 1.5723x; 1.0774x over previous
#include <cuda_runtime.h>
#include <cuda_bf16.h>
#include <math.h>
#include <stdint.h>

// ---------------- scratch (static device globals; no allocation) ----------------
__device__ float g_featA[32u*256*512];     // conv4 out fp32 (pre-normalize)
__device__ float g_featB[32u*256*512];
__device__ float g_corr[32u*256*256];
__device__ float g_r1[32u*10*10*128];
__device__ float g_r2[32u*6*6*64];
__device__ float g_geo[32*18];

// bf16 hi/mid/lo split buffers (each tensor split exactly once)
__device__ __nv_bfloat16 g_s1h[32u*128*128*64], g_s1m[32u*128*128*64], g_s1l[32u*128*128*64];
__device__ __nv_bfloat16 g_s2h[32u*64*64*128],  g_s2m[32u*64*64*128],  g_s2l[32u*64*64*128];
__device__ __nv_bfloat16 g_s3h[32u*32*32*256],  g_s3m[32u*32*32*256],  g_s3l[32u*32*32*256];
__device__ __nv_bfloat16 g_fAh[32u*256*512],    g_fAm[32u*256*512],    g_fAl[32u*256*512];
__device__ __nv_bfloat16 g_fBh[32u*256*512],    g_fBm[32u*256*512],    g_fBl[32u*256*512];
__device__ __nv_bfloat16 g_ch[32u*256*256],     g_cm[32u*256*256],     g_cl[32u*256*256];
__device__ __nv_bfloat16 g_wh[3153920],         g_wm[3153920],         g_wl[3153920];

// fp32 -> 3-term bf16 split (hi+mid+lo ~ 24 mantissa bits), two floats packed
// per u32 at each level (first arg in low half = lower k index).
__device__ __forceinline__ void cvt3(float a, float b,
                                     uint32_t& hi, uint32_t& mid, uint32_t& lo) {
    __nv_bfloat162 h = __floats2bfloat162_rn(a, b);
    float ra = a - __bfloat162float(__low2bfloat16(h));
    float rb = b - __bfloat162float(__high2bfloat16(h));
    __nv_bfloat162 m = __floats2bfloat162_rn(ra, rb);
    ra -= __bfloat162float(__low2bfloat16(m));
    rb -= __bfloat162float(__high2bfloat16(m));
    __nv_bfloat162 l = __floats2bfloat162_rn(ra, rb);
    hi  = reinterpret_cast<uint32_t&>(h);
    mid = reinterpret_cast<uint32_t&>(m);
    lo  = reinterpret_cast<uint32_t&>(l);
}

__device__ __forceinline__ void mma16816(float* d, const uint32_t* a, const uint32_t* b) {
    asm volatile(
        "mma.sync.aligned.m16n8k16.row.col.f32.bf16.bf16.f32 "
        "{%0,%1,%2,%3}, {%4,%5,%6,%7}, {%8,%9}, {%0,%1,%2,%3};"
        : "+f"(d[0]), "+f"(d[1]), "+f"(d[2]), "+f"(d[3])
        : "r"(a[0]), "r"(a[1]), "r"(a[2]), "r"(a[3]), "r"(b[0]), "r"(b[1]));
}
__device__ __forceinline__ void mma16816_zc(float* d, const uint32_t* a, const uint32_t* b) {
    asm volatile(
        "mma.sync.aligned.m16n8k16.row.col.f32.bf16.bf16.f32 "
        "{%0,%1,%2,%3}, {%4,%5,%6,%7}, {%8,%9}, {%10,%11,%12,%13};"
        : "=f"(d[0]), "=f"(d[1]), "=f"(d[2]), "=f"(d[3])
        : "r"(a[0]), "r"(a[1]), "r"(a[2]), "r"(a[3]), "r"(b[0]), "r"(b[1]),
          "f"(0.f), "f"(0.f), "f"(0.f), "f"(0.f));
}
__device__ __forceinline__ void ldm4(uint32_t* r, uint32_t addr) {
    asm volatile("ldmatrix.sync.aligned.m8n8.x4.shared.b16 {%0,%1,%2,%3}, [%4];"
                 : "=r"(r[0]), "=r"(r[1]), "=r"(r[2]), "=r"(r[3]) : "r"(addr));
}
__device__ __forceinline__ uint32_t smem_addr_u32(const void* p) {
    uint32_t a;
    asm("{ .reg .u64 t; cvta.to.shared.u64 t, %1; cvt.u32.u64 %0, t; }" : "=r"(a) : "l"(p));
    return a;
}

// smem layout in u32 units: rows padded to 36 u32 (144B: 16B-aligned rows for
// ldmatrix; 8 consecutive rows cover all 8 16B bank-groups -> conflict-free)
#define A_STRIDE 36
#define SM_AHI  0
#define SM_AMID (128*36)
#define SM_ALO  (2*128*36)
#define SM_BHI  (3*128*36)
#define SM_BMID (3*128*36 + 64*36)
#define SM_BLO  (3*128*36 + 2*64*36)
#define SM_U32  (3*128*36 + 3*64*36)     // 20736 u32 = 82944 bytes

// ====== bf16x6 tensor-core implicit-GEMM conv / GEMM ======
// All operands PRE-SPLIT into bf16 hi/mid/lo in gmem: producers are pure
// uint4 copies (no convert math in the mainloop). Per-k16 MMA windows are
// drained into IEEE-RN fp32 regs (accumulator-truncation fix, R11).
// Block tile M=128, N=64, BK=64; 8 warps (4M x 2N), warp tile 32x32.
template<int CIN,int COUT,int HIN,int WIN,int HOUT,int WOUT,int KH,int KW,int STRIDE,
         bool MGUARD,bool BKM,int NTOT,bool WRITEF32,bool WRITESPLIT,bool RELU>
__global__ __launch_bounds__(256, 2)
void conv_mma(const __nv_bfloat16* __restrict__ inh, const __nv_bfloat16* __restrict__ inm,
              const __nv_bfloat16* __restrict__ inl,
              const __nv_bfloat16* __restrict__ wth, const __nv_bfloat16* __restrict__ wtm,
              const __nv_bfloat16* __restrict__ wtl,
              float* __restrict__ outf,
              __nv_bfloat16* __restrict__ outh, __nv_bfloat16* __restrict__ outm,
              __nv_bfloat16* __restrict__ outl)
{
    constexpr int M   = HOUT * WOUT;
    constexpr int CPT = CIN / 64;
    constexpr int KCH = KH * KW * CPT;

    extern __shared__ uint32_t smem[];
    uint32_t* Ahi  = smem + SM_AHI;
    uint32_t* Amid = smem + SM_AMID;
    uint32_t* Alo  = smem + SM_ALO;
    uint32_t* Bhi  = smem + SM_BHI;
    uint32_t* Bmid = smem + SM_BMID;
    uint32_t* Blo  = smem + SM_BLO;
    uint32_t sb = smem_addr_u32(smem);
    uint32_t sbAhi = sb + SM_AHI*4,  sbAmid = sb + SM_AMID*4, sbAlo = sb + SM_ALO*4;
    uint32_t sbBhi = sb + SM_BHI*4,  sbBmid = sb + SM_BMID*4, sbBlo = sb + SM_BLO*4;

    int tid = threadIdx.x;
    int wid = tid >> 5, lane = tid & 31;
    int m0 = blockIdx.x * 128, n0 = blockIdx.y * 64;
    int img = blockIdx.z;

    // A producer: 2 threads per row, 32 k each
    int ar = tid >> 1;
    int ak0 = (tid & 1) * 32;
    int am = m0 + ar;
    int aoh = am / WOUT, aow = am % WOUT;

    // B producer: 4 threads per row, 16 k each
    int br = tid >> 2;
    int bk0 = (tid & 3) * 16;

    // warp tiling
    int wm = wid >> 1, wn = wid & 1;          // warp m 0..3, n 0..1
    int g = lane >> 2, t = lane & 3;

    // ldmatrix per-lane address offsets (u32 units)
    int arsel = ((lane >> 3) & 1) * 8 + (lane & 7);
    int acol  = (lane >> 4) * 4;
    int aoffs[2];
    #pragma unroll
    for (int mt = 0; mt < 2; ++mt)
        aoffs[mt] = (wm*32 + mt*16 + arsel) * A_STRIDE + acol;
    int brsel = ((lane >> 4) & 1) * 8 + (lane & 7);
    int bcol  = ((lane >> 3) & 1) * 4;
    int boffs[2];
    #pragma unroll
    for (int ntp = 0; ntp < 2; ++ntp)
        boffs[ntp] = (wn*32 + ntp*16 + brsel) * A_STRIDE + bcol;

    float acc[2][4][4];
    #pragma unroll
    for (int i = 0; i < 2; ++i)
        #pragma unroll
        for (int j = 0; j < 4; ++j)
            #pragma unroll
            for (int q = 0; q < 4; ++q) acc[i][j][q] = 0.f;

    for (int c = 0; c < KCH; ++c) {
        int tap  = c / CPT;
        int cin0 = (c % CPT) * 64;
        int kh = tap / KW, kw = tap - kh * KW;

        // ---- A: 128 x 64 bf16x3 pre-split, pure uint4 copy
        {
            int ih = aoh * STRIDE + kh, iw = aow * STRIDE + kw;
            bool ok = (ih < HIN) && (iw < WIN);
            if (MGUARD) ok = ok && (am < M);
            size_t off = (size_t)img * HIN * WIN * CIN + ((size_t)ih * WIN + iw) * CIN
                       + cin0 + ak0;
            const uint4* ph = reinterpret_cast<const uint4*>(inh + off);
            const uint4* pm = reinterpret_cast<const uint4*>(inm + off);
            const uint4* pl = reinterpret_cast<const uint4*>(inl + off);
            uint4 z = make_uint4(0u,0u,0u,0u);
            #pragma unroll
            for (int jj = 0; jj < 4; ++jj) {
                uint4 vh = ok ? ph[jj] : z;
                uint4 vm = ok ? pm[jj] : z;
                uint4 vl = ok ? pl[jj] : z;
                int p = (ak0 >> 1) + jj*4;
                *reinterpret_cast<uint4*>(&Ahi [ar*A_STRIDE + p]) = vh;
                *reinterpret_cast<uint4*>(&Amid[ar*A_STRIDE + p]) = vm;
                *reinterpret_cast<uint4*>(&Alo [ar*A_STRIDE + p]) = vl;
            }
        }
        // ---- B: 64(n) x 64(k), pre-split k-major source
        {
            size_t off = BKM
                ? ((size_t)img * NTOT + n0 + br) * CIN + cin0 + bk0
                : ((size_t)tap * COUT + n0 + br) * CIN + cin0 + bk0;
            const uint4* ph = reinterpret_cast<const uint4*>(wth + off);
            const uint4* pm = reinterpret_cast<const uint4*>(wtm + off);
            const uint4* pl = reinterpret_cast<const uint4*>(wtl + off);
            #pragma unroll
            for (int jj = 0; jj < 2; ++jj) {
                int p = (bk0 >> 1) + jj*4;
                *reinterpret_cast<uint4*>(&Bhi [br*A_STRIDE + p]) = ph[jj];
                *reinterpret_cast<uint4*>(&Bmid[br*A_STRIDE + p]) = pm[jj];
                *reinterpret_cast<uint4*>(&Blo [br*A_STRIDE + p]) = pl[jj];
            }
        }
        __syncthreads();

        // ---- compute: 4 k16 steps; fresh MMA window per step, FADD drain
        #pragma unroll
        for (int ks = 0; ks < 4; ++ks) {
            int kp = ks * 8;
            uint32_t ah[2][4], am_[2][4], al[2][4];
            #pragma unroll
            for (int mt = 0; mt < 2; ++mt) {
                ldm4(ah[mt],  sbAhi  + (aoffs[mt] + kp) * 4);
                ldm4(am_[mt], sbAmid + (aoffs[mt] + kp) * 4);
                ldm4(al[mt],  sbAlo  + (aoffs[mt] + kp) * 4);
            }
            #pragma unroll
            for (int ntp = 0; ntp < 2; ++ntp) {
                uint32_t bh[4], bm[4], bl[4];
                ldm4(bh, sbBhi  + (boffs[ntp] + kp) * 4);
                ldm4(bm, sbBmid + (boffs[ntp] + kp) * 4);
                ldm4(bl, sbBlo  + (boffs[ntp] + kp) * 4);
                #pragma unroll
                for (int half = 0; half < 2; ++half) {
                    int nt = ntp * 2 + half;
                    const uint32_t* pbh = bh + half*2;
                    const uint32_t* pbm = bm + half*2;
                    const uint32_t* pbl = bl + half*2;
                    #pragma unroll
                    for (int mt = 0; mt < 2; ++mt) {
                        float tmp[4];
                        mma16816_zc(tmp, ah[mt],  pbh);
                        mma16816(tmp, ah[mt],  pbm);
                        mma16816(tmp, am_[mt], pbh);
                        mma16816(tmp, ah[mt],  pbl);
                        mma16816(tmp, am_[mt], pbm);
                        mma16816(tmp, al[mt],  pbh);
                        acc[mt][nt][0] += tmp[0];
                        acc[mt][nt][1] += tmp[1];
                        acc[mt][nt][2] += tmp[2];
                        acc[mt][nt][3] += tmp[3];
                    }
                }
            }
        }
        __syncthreads();
    }

    // ---- epilogue
    #pragma unroll
    for (int mt = 0; mt < 2; ++mt) {
        #pragma unroll
        for (int half = 0; half < 2; ++half) {
            int row = m0 + wm * 32 + mt * 16 + g + half * 8;
            if (MGUARD && row >= M) continue;
            size_t base = ((size_t)img * M + row) * COUT + n0 + wn * 32;
            #pragma unroll
            for (int nt = 0; nt < 4; ++nt) {
                float x0 = acc[mt][nt][half*2 + 0];
                float x1 = acc[mt][nt][half*2 + 1];
                if (RELU) { x0 = fmaxf(x0, 0.f); x1 = fmaxf(x1, 0.f); }
                size_t idx = base + nt*8 + 2*t;
                if (WRITEF32)
                    *reinterpret_cast<float2*>(outf + idx) = make_float2(x0, x1);
                if (WRITESPLIT) {
                    uint32_t h, m, l;
                    cvt3(x0, x1, h, m, l);
                    *reinterpret_cast<uint32_t*>(outh + idx) = h;
                    *reinterpret_cast<uint32_t*>(outm + idx) = m;
                    *reinterpret_cast<uint32_t*>(outl + idx) = l;
                }
            }
        }
    }
}

// ---------------- weight transpose + split: (tap,cin,cout)->(tap,cout,cin) ----
__global__ void split_w(const float* __restrict__ in,
                        __nv_bfloat16* __restrict__ oh, __nv_bfloat16* __restrict__ om,
                        __nv_bfloat16* __restrict__ ol,
                        int cin, int cout, int total)
{
    int idx = blockIdx.x * 256 + threadIdx.x;
    if (idx >= total) return;
    int n = idx % cout;
    int rest = idx / cout;
    int ci = rest % cin;
    int tap = rest / cin;
    float w = in[idx];
    __nv_bfloat16 h = __float2bfloat16(w);
    float r = w - __bfloat162float(h);
    __nv_bfloat16 m = __float2bfloat16(r);
    r -= __bfloat162float(m);
    __nv_bfloat16 l = __float2bfloat16(r);
    size_t o = ((size_t)tap * cout + n) * cin + ci;
    oh[o] = h; om[o] = m; ol[o] = l;
}

// ---------------- conv1: 256x256x3 -> 128x128x64 split, stride 2, pad_lo=0 ----
__global__ void conv1_kernel(const float* __restrict__ in, const float* __restrict__ w,
                             __nv_bfloat16* __restrict__ oh, __nv_bfloat16* __restrict__ om,
                             __nv_bfloat16* __restrict__ ol)
{
    int idx = blockIdx.x * 256 + threadIdx.x;   // handles output elems 2*idx, 2*idx+1
    int e = idx * 2;
    int oc = e & 63;                             // even
    int p  = e >> 6;
    int ow = p & 127; p >>= 7;
    int ohh = p & 127; p >>= 7;
    int b  = p;
    float a0 = 0.f, a1 = 0.f;
    #pragma unroll
    for (int kh = 0; kh < 3; ++kh) {
        int ih = ohh * 2 + kh;
        if (ih >= 256) continue;
        #pragma unroll
        for (int kw = 0; kw < 3; ++kw) {
            int iw = ow * 2 + kw;
            if (iw >= 256) continue;
            const float* ip = in + ((size_t)(b * 256 + ih) * 256 + iw) * 3;
            const float* wp = w + ((kh * 3 + kw) * 3) * 64 + oc;
            a0 += ip[0] * wp[0] + ip[1] * wp[64]  + ip[2] * wp[128];
            a1 += ip[0] * wp[1] + ip[1] * wp[65]  + ip[2] * wp[129];
        }
    }
    a0 = fmaxf(a0, 0.f);
    a1 = fmaxf(a1, 0.f);
    uint32_t h, m, l;
    cvt3(a0, a1, h, m, l);
    *reinterpret_cast<uint32_t*>(oh + e) = h;
    *reinterpret_cast<uint32_t*>(om + e) = m;
    *reinterpret_cast<uint32_t*>(ol + e) = l;
}

// ---------------- L2-normalize 512ch fp32 -> bf16x3 split ----------------------
__global__ void normalize_split(const float* __restrict__ feat,
                                __nv_bfloat16* __restrict__ oh, __nv_bfloat16* __restrict__ om,
                                __nv_bfloat16* __restrict__ ol)
{
    size_t row = blockIdx.x;
    const float* p = feat + row * 512;
    int tid = threadIdx.x;   // 128
    float4 v = *reinterpret_cast<const float4*>(p + tid * 4);
    float s = v.x*v.x + v.y*v.y + v.z*v.z + v.w*v.w;
    for (int o = 16; o > 0; o >>= 1) s += __shfl_down_sync(0xffffffffu, s, o);
    __shared__ float sw[4];
    __shared__ float sscale;
    if ((tid & 31) == 0) sw[tid >> 5] = s;
    __syncthreads();
    if (tid == 0) sscale = 1.f / (sqrtf(sw[0] + sw[1] + sw[2] + sw[3]) + 1e-6f);
    __syncthreads();
    float sc = sscale;
    v.x *= sc; v.y *= sc; v.z *= sc; v.w *= sc;
    uint32_t h0, m0, l0, h1, m1, l1;
    cvt3(v.x, v.y, h0, m0, l0);
    cvt3(v.z, v.w, h1, m1, l1);
    size_t base = row * 512 + tid * 4;
    *reinterpret_cast<uint32_t*>(oh + base)     = h0;
    *reinterpret_cast<uint32_t*>(oh + base + 2) = h1;
    *reinterpret_cast<uint32_t*>(om + base)     = m0;
    *reinterpret_cast<uint32_t*>(om + base + 2) = m1;
    *reinterpret_cast<uint32_t*>(ol + base)     = l0;
    *reinterpret_cast<uint32_t*>(ol + base + 2) = l1;
}

// ---------------- legacy FFMA igemm (small r2 conv only) ----------------------
template<int CIN,int COUT,int HIN,int WIN,int HOUT,int WOUT,int KH,int KW,int STRIDE,bool MGUARD>
__global__ __launch_bounds__(256)
void conv_igemm(const float* __restrict__ in, const float* __restrict__ wt,
                float* __restrict__ out)
{
    constexpr int M   = HOUT * WOUT;
    constexpr int CPT = CIN / 64;
    constexpr int KCH = KH * KW * CPT;
    __shared__ __align__(16) float As[64][68];
    __shared__ __align__(16) float Bs[64][68];

    int tid = threadIdx.x;
    int m0 = blockIdx.x * 64, n0 = blockIdx.y * 64;
    int img = blockIdx.z;
    const float* inb = in + (size_t)img * HIN * WIN * CIN;

    int lr = tid >> 2;
    int lc = (tid & 3) << 4;
    int m  = m0 + lr;
    int oh = m / WOUT, ow = m % WOUT;
    int ty = tid >> 4, tx = tid & 15;

    float acc[4][4] = {};
    for (int c = 0; c < KCH; ++c) {
        int tap  = c / CPT;
        int cin0 = (c % CPT) * 64;
        int kh = tap / KW, kw = tap - kh * KW;
        int ih = oh * STRIDE + kh, iw = ow * STRIDE + kw;
        bool ok = (ih < HIN) && (iw < WIN);
        if (MGUARD) ok = ok && (m < M);
        const float* ap = inb + ((size_t)ih * WIN + iw) * CIN + cin0 + lc;
        #pragma unroll
        for (int t = 0; t < 4; ++t) {
            float4 v = ok ? *reinterpret_cast<const float4*>(ap + 4 * t)
                          : make_float4(0.f, 0.f, 0.f, 0.f);
            As[lc + 4*t + 0][lr] = v.x; As[lc + 4*t + 1][lr] = v.y;
            As[lc + 4*t + 2][lr] = v.z; As[lc + 4*t + 3][lr] = v.w;
        }
        const float* bp = wt + ((size_t)tap * CIN + cin0 + lr) * COUT + n0 + lc;
        #pragma unroll
        for (int t = 0; t < 4; ++t)
            *reinterpret_cast<float4*>(&Bs[lr][lc + 4*t]) =
                *reinterpret_cast<const float4*>(bp + 4 * t);
        __syncthreads();
        #pragma unroll
        for (int kk = 0; kk < 64; ++kk) {
            float4 av = *reinterpret_cast<const float4*>(&As[kk][ty * 4]);
            float4 bv = *reinterpret_cast<const float4*>(&Bs[kk][tx * 4]);
            float ar[4] = {av.x, av.y, av.z, av.w};
            float br[4] = {bv.x, bv.y, bv.z, bv.w};
            #pragma unroll
            for (int i = 0; i < 4; ++i)
                #pragma unroll
                for (int j = 0; j < 4; ++j)
                    acc[i][j] += ar[i] * br[j];
        }
        __syncthreads();
    }
    #pragma unroll
    for (int i = 0; i < 4; ++i) {
        int mm = m0 + ty * 4 + i;
        if (MGUARD && mm >= M) continue;
        float4 v = make_float4(fmaxf(acc[i][0], 0.f), fmaxf(acc[i][1], 0.f),
                               fmaxf(acc[i][2], 0.f), fmaxf(acc[i][3], 0.f));
        *reinterpret_cast<float4*>(out + ((size_t)img * M + mm) * COUT + n0 + tx * 4) = v;
    }
}

// ---------------- dense: geo = r2_flat(2304) @ Wd(2304,18) + bd ---------------
__global__ void dense_kernel(const float* __restrict__ x, const float* __restrict__ Wd,
                             const float* __restrict__ bd, float* __restrict__ geo)
{
    int b = blockIdx.x;
    int o = threadIdx.x >> 5;
    int lane = threadIdx.x & 31;
    const float* xb = x + b * 2304;
    float acc = 0.f;
    for (int t = lane; t < 2304; t += 32)
        acc += xb[t] * Wd[t * 18 + o];
    for (int s = 16; s > 0; s >>= 1) acc += __shfl_down_sync(0xffffffffu, acc, s);
    if (lane == 0) geo[b * 18 + o] = acc + bd[o];
}

// ---------------- TPS fit + masked sum ----------------------------------------
__global__ void tps_sum_kernel(const float* __restrict__ geo, const float* __restrict__ corr,
                               float* __restrict__ out)
{
    int b = blockIdx.x, tid = threadIdx.x;
    __shared__ float sdx[9], sdy[9], swx[9], swy[9], sax[3], say[3];
    __shared__ float red[256];

    if (tid == 0) {
        const float srcx[9] = {0.f, 0.5f, 1.f, 0.f, 0.5f, 1.f, 0.f, 5.f, 1.f};
        const float srcy[9] = {0.f, 0.f,  0.f, 0.5f,0.5f, 0.5f,1.f, 1.f, 1.f};
        float dx9[9], dy9[9], vx[9], vy[9];
        for (int c = 0; c < 9; ++c) {
            float mx_ = geo[b * 18 + 2 * c], my_ = geo[b * 18 + 2 * c + 1];
            dx9[c] = srcx[c] + mx_;  dy9[c] = srcy[c] + my_;
            vx[c] = -mx_;            vy[c] = -my_;
        }
        float Mx[12][14];
        for (int i = 0; i < 12; ++i)
            for (int j = 0; j < 14; ++j) Mx[i][j] = 0.f;
        for (int i = 0; i < 9; ++i) {
            for (int j = 0; j < 9; ++j) {
                float ddx = dx9[i] - dx9[j], ddy = dy9[i] - dy9[j];
                float r = sqrtf(ddx * ddx + ddy * ddy + 1e-12f);
                Mx[i][j] = r * r * logf(r + 1e-6f);
            }
            Mx[i][9] = 1.f; Mx[i][10] = dx9[i]; Mx[i][11] = dy9[i];
            Mx[9][i] = 1.f; Mx[10][i] = dx9[i]; Mx[11][i] = dy9[i];
            Mx[i][12] = vx[i]; Mx[i][13] = vy[i];
        }
        for (int k = 0; k < 12; ++k) {
            int piv = k; float best = fabsf(Mx[k][k]);
            for (int i = k + 1; i < 12; ++i) {
                float a = fabsf(Mx[i][k]);
                if (a > best) { best = a; piv = i; }
            }
            if (piv != k)
                for (int j = k; j < 14; ++j) {
                    float t = Mx[k][j]; Mx[k][j] = Mx[piv][j]; Mx[piv][j] = t;
                }
            for (int i = k + 1; i < 12; ++i) {
                float f = Mx[i][k] / Mx[k][k];
                for (int j = k + 1; j < 14; ++j) Mx[i][j] -= f * Mx[k][j];
                Mx[i][k] = 0.f;
            }
        }
        float thx[12], thy[12];
        for (int k = 11; k >= 0; --k) {
            float sx = Mx[k][12], sy = Mx[k][13];
            for (int j = k + 1; j < 12; ++j) { sx -= Mx[k][j] * thx[j]; sy -= Mx[k][j] * thy[j]; }
            thx[k] = sx / Mx[k][k];  thy[k] = sy / Mx[k][k];
        }
        float s8x = 0.f, s8y = 0.f;
        for (int c = 1; c < 9; ++c) { s8x += thx[c]; s8y += thy[c]; }
        swx[0] = -s8x; swy[0] = -s8y;
        for (int c = 1; c < 9; ++c) { swx[c] = thx[c]; swy[c] = thy[c]; }
        sax[0] = thx[9]; sax[1] = thx[10]; sax[2] = thx[11];
        say[0] = thy[9]; say[1] = thy[10]; say[2] = thy[11];
        for (int c = 0; c < 9; ++c) { sdx[c] = dx9[c]; sdy[c] = dy9[c]; }
    }
    __syncthreads();

    int r = tid >> 4, c = tid & 15;
    float px = c * (1.f / 15.f), py = r * (1.f / 15.f);
    float zx = 0.f, zy = 0.f;
    #pragma unroll
    for (int q = 0; q < 9; ++q) {
        float ddx = px - sdx[q], ddy = py - sdy[q];
        float rr = sqrtf(ddx * ddx + ddy * ddy + 1e-12f);
        float u = rr * rr * logf(rr + 1e-6f);
        zx += u * swx[q]; zy += u * swy[q];
    }
    zx += sax[0] + px * sax[1] + py * sax[2];
    zy += say[0] + px * say[1] + py * say[2];
    float axv = (px + zx) * 15.f;
    float ayv = (py + zy) * 15.f;

    const float* col = corr + (size_t)b * 65536 + tid;
    float s = 0.f;
    for (int i = 0; i < 16; ++i) {
        if (fabsf((float)i - ayv) > 1.f) continue;
        const float* rp = col + i * 4096;
        for (int j = 0; j < 16; ++j)
            if (fabsf((float)j - axv) <= 1.f) s += rp[j * 256];
    }
    red[tid] = s;
    __syncthreads();
    for (int o = 128; o > 0; o >>= 1) {
        if (tid < o) red[tid] += red[tid + o];
        __syncthreads();
    }
    if (tid == 0) out[b] = red[0];
}

// ---------------- launch ------------------------------------------------------
extern "C" void kernel_launch(void* const* d_in, const int* in_sizes, int n_in,
                              void* d_out, int out_size)
{
    const float* imgA = (const float*)d_in[0];
    const float* imgB = (const float*)d_in[1];
    const float* W1   = (const float*)d_in[2];
    const float* W2   = (const float*)d_in[3];
    const float* W3   = (const float*)d_in[4];
    const float* W4   = (const float*)d_in[5];
    const float* Wr1  = (const float*)d_in[6];
    const float* Wr2  = (const float*)d_in[7];
    const float* Wd   = (const float*)d_in[8];
    const float* bd   = (const float*)d_in[9];
    float* out = (float*)d_out;

    float *featA, *featB, *corr, *r1, *r2, *geo;
    cudaGetSymbolAddress((void**)&featA, g_featA);
    cudaGetSymbolAddress((void**)&featB, g_featB);
    cudaGetSymbolAddress((void**)&corr,  g_corr);
    cudaGetSymbolAddress((void**)&r1,    g_r1);
    cudaGetSymbolAddress((void**)&r2,    g_r2);
    cudaGetSymbolAddress((void**)&geo,   g_geo);

    __nv_bfloat16 *s1h,*s1m,*s1l,*s2h,*s2m,*s2l,*s3h,*s3m,*s3l;
    __nv_bfloat16 *fAh,*fAm,*fAl,*fBh,*fBm,*fBl,*ch,*cm,*cl,*wh,*wm,*wl;
    cudaGetSymbolAddress((void**)&s1h, g_s1h); cudaGetSymbolAddress((void**)&s1m, g_s1m);
    cudaGetSymbolAddress((void**)&s1l, g_s1l);
    cudaGetSymbolAddress((void**)&s2h, g_s2h); cudaGetSymbolAddress((void**)&s2m, g_s2m);
    cudaGetSymbolAddress((void**)&s2l, g_s2l);
    cudaGetSymbolAddress((void**)&s3h, g_s3h); cudaGetSymbolAddress((void**)&s3m, g_s3m);
    cudaGetSymbolAddress((void**)&s3l, g_s3l);
    cudaGetSymbolAddress((void**)&fAh, g_fAh); cudaGetSymbolAddress((void**)&fAm, g_fAm);
    cudaGetSymbolAddress((void**)&fAl, g_fAl);
    cudaGetSymbolAddress((void**)&fBh, g_fBh); cudaGetSymbolAddress((void**)&fBm, g_fBm);
    cudaGetSymbolAddress((void**)&fBl, g_fBl);
    cudaGetSymbolAddress((void**)&ch, g_ch); cudaGetSymbolAddress((void**)&cm, g_cm);
    cudaGetSymbolAddress((void**)&cl, g_cl);
    cudaGetSymbolAddress((void**)&wh, g_wh); cudaGetSymbolAddress((void**)&wm, g_wm);
    cudaGetSymbolAddress((void**)&wl, g_wl);

    // transposed+split weight regions (element offsets)
    const size_t O_W2 = 0, O_W3 = 73728, O_W4 = 368640, O_Wr1 = 1548288;
    split_w<<<(73728 + 255)/256, 256>>>(W2,  wh + O_W2,  wm + O_W2,  wl + O_W2,  64, 128, 73728);
    split_w<<<(294912 + 255)/256, 256>>>(W3, wh + O_W3,  wm + O_W3,  wl + O_W3,  128, 256, 294912);
    split_w<<<(1179648 + 255)/256, 256>>>(W4, wh + O_W4, wm + O_W4, wl + O_W4, 256, 512, 1179648);
    split_w<<<(1605632 + 255)/256, 256>>>(Wr1, wh + O_Wr1, wm + O_Wr1, wl + O_Wr1, 256, 128, 1605632);

    const int SMB = SM_U32 * 4;    // 82944 bytes dynamic smem
    auto mm2 = conv_mma<64, 128, 128, 128, 64, 64, 3, 3, 2, false, false, 0, false, true, true>;
    auto mm3 = conv_mma<128, 256, 64, 64, 32, 32, 3, 3, 2, false, false, 0, false, true, true>;
    auto mm4 = conv_mma<256, 512, 32, 32, 16, 16, 3, 3, 2, false, false, 0, true, false, true>;
    auto mmc = conv_mma<512, 256, 16, 16, 16, 16, 1, 1, 1, false, true, 256, true, true, false>;
    auto mr1 = conv_mma<256, 128, 16, 16, 10, 10, 7, 7, 1, true, false, 0, true, false, true>;
    cudaFuncSetAttribute(mm2, cudaFuncAttributeMaxDynamicSharedMemorySize, SMB);
    cudaFuncSetAttribute(mm3, cudaFuncAttributeMaxDynamicSharedMemorySize, SMB);
    cudaFuncSetAttribute(mm4, cudaFuncAttributeMaxDynamicSharedMemorySize, SMB);
    cudaFuncSetAttribute(mmc, cudaFuncAttributeMaxDynamicSharedMemorySize, SMB);
    cudaFuncSetAttribute(mr1, cudaFuncAttributeMaxDynamicSharedMemorySize, SMB);

    for (int im = 0; im < 2; ++im) {
        const float* img = im ? imgB : imgA;
        float* feat = im ? featB : featA;
        __nv_bfloat16 *fh = im ? fBh : fAh, *fm = im ? fBm : fAm, *fl = im ? fBl : fAl;
        conv1_kernel<<<65536, 256>>>(img, W1, s1h, s1m, s1l);
        mm2<<<dim3(32, 2, 32), 256, SMB>>>(s1h, s1m, s1l, wh + O_W2, wm + O_W2, wl + O_W2,
                                           nullptr, s2h, s2m, s2l);
        mm3<<<dim3(8, 4, 32), 256, SMB>>>(s2h, s2m, s2l, wh + O_W3, wm + O_W3, wl + O_W3,
                                          nullptr, s3h, s3m, s3l);
        mm4<<<dim3(2, 8, 32), 256, SMB>>>(s3h, s3m, s3l, wh + O_W4, wm + O_W4, wl + O_W4,
                                          feat, nullptr, nullptr, nullptr);
        normalize_split<<<8192, 128>>>(feat, fh, fm, fl);
    }

    mmc<<<dim3(2, 4, 32), 256, SMB>>>(fAh, fAm, fAl, fBh, fBm, fBl, corr, ch, cm, cl);

    mr1<<<dim3(1, 2, 32), 256, SMB>>>(ch, cm, cl, wh + O_Wr1, wm + O_Wr1, wl + O_Wr1,
                                      r1, nullptr, nullptr, nullptr);
    conv_igemm<128, 64, 10, 10, 6, 6, 5, 5, 1, true>
        <<<dim3(1, 1, 32), 256>>>(r1, Wr2, r2);

    dense_kernel<<<32, 576>>>(r2, Wd, bd, geo);
    tps_sum_kernel<<<32, 256>>>(geo, corr, out);
}